// round 12
// baseline (speedup 1.0000x reference)
#include <cuda_runtime.h>
#include <cuda_bf16.h>
#include <cstdint>

// =====================================================================
// ATQCNN factorization:
//   U = fixed 128x128 orthogonal circuit matrix (wires 0..6; 7,8 inert)
//   Y[b] = U x[b];  q[b,k] = sum_{m&3==k} Y[b,m]^2;  out = softmax(q/sum q)
// Kernel 1: warp-per-basis register simulation -> U as bf16 split
//           (U = U_hi + U_lo residual; 3-pass product err ~4e-7 measured).
// Kernel 2: mma.sync (m16n8k16 bf16) GEMM, 3 accumulated passes
//           (Xhi·Uhi + Xlo·Uhi + Xhi·Ulo). 128 CTAs x 8 warps
//           (2m x 4n split), B fragments shared across hi/lo passes,
//           cross-warp q-combine via smem, softmax epilogue.
// =====================================================================

__device__ __align__(16) __nv_bfloat16 g_Uhi[128 * 128];  // [m][i] row-major
__device__ __align__(16) __nv_bfloat16 g_Ulo[128 * 128];  // [m][i] row-major

// --------------------- warp-MMA helpers -------------------------------
__device__ __forceinline__ uint32_t smem_to_u32(const void* p) {
    uint32_t a;
    asm("{ .reg .u64 t; cvta.to.shared.u64 t, %1; cvt.u32.u64 %0, t; }"
        : "=r"(a) : "l"(p));
    return a;
}
__device__ __forceinline__ void ldsm4(uint32_t& r0, uint32_t& r1,
                                      uint32_t& r2, uint32_t& r3, uint32_t a) {
    asm volatile("ldmatrix.sync.aligned.m8n8.x4.shared.b16 {%0,%1,%2,%3}, [%4];"
                 : "=r"(r0), "=r"(r1), "=r"(r2), "=r"(r3) : "r"(a));
}
__device__ __forceinline__ void ldsm2(uint32_t& r0, uint32_t& r1, uint32_t a) {
    asm volatile("ldmatrix.sync.aligned.m8n8.x2.shared.b16 {%0,%1}, [%2];"
                 : "=r"(r0), "=r"(r1) : "r"(a));
}
__device__ __forceinline__ void mma_bf16(float* d, const uint32_t* a,
                                         uint32_t b0, uint32_t b1) {
    asm volatile(
        "mma.sync.aligned.m16n8k16.row.col.f32.bf16.bf16.f32 "
        "{%0,%1,%2,%3}, {%4,%5,%6,%7}, {%8,%9}, {%0,%1,%2,%3};"
        : "+f"(d[0]), "+f"(d[1]), "+f"(d[2]), "+f"(d[3])
        : "r"(a[0]), "r"(a[1]), "r"(a[2]), "r"(a[3]), "r"(b0), "r"(b1));
}
__device__ __forceinline__ uint32_t pack_bf2(__nv_bfloat16 a, __nv_bfloat16 b) {
    __nv_bfloat162 t = __halves2bfloat162(a, b);
    return *reinterpret_cast<uint32_t*>(&t);
}

// --------------------- gate primitives (register sim) -----------------
template<int P>
__device__ __forceinline__ void ry_p(float a[4], float c, float s, int lane) {
    if constexpr (P == 0) {
        float n0 = c * a[0] - s * a[1];
        float n1 = fmaf(s, a[0], c * a[1]);
        float n2 = c * a[2] - s * a[3];
        float n3 = fmaf(s, a[2], c * a[3]);
        a[0] = n0; a[1] = n1; a[2] = n2; a[3] = n3;
    } else if constexpr (P == 1) {
        float n0 = c * a[0] - s * a[2];
        float n2 = fmaf(s, a[0], c * a[2]);
        float n1 = c * a[1] - s * a[3];
        float n3 = fmaf(s, a[1], c * a[3]);
        a[0] = n0; a[1] = n1; a[2] = n2; a[3] = n3;
    } else {
        constexpr int M = 1 << (P - 2);
        const float sgn = (lane & M) ? s : -s;
        #pragma unroll
        for (int r = 0; r < 4; ++r) {
            float pr = __shfl_xor_sync(0xffffffffu, a[r], M);
            a[r] = fmaf(sgn, pr, c * a[r]);
        }
    }
}
template<int W>
__device__ __forceinline__ void ry_w(float a[4], float2 cs, int lane) {
    ry_p<6 - W>(a, cs.x, cs.y, lane);
}
template<int PC, int PT>
__device__ __forceinline__ void cnot_p(float a[4], int lane) {
    if constexpr (PT >= 2) {
        constexpr int MT = 1 << (PT - 2);
        if constexpr (PC >= 2) {
            constexpr int MC = 1 << (PC - 2);
            const bool ctl = (lane & MC) != 0;
            #pragma unroll
            for (int r = 0; r < 4; ++r) {
                float pr = __shfl_xor_sync(0xffffffffu, a[r], MT);
                a[r] = ctl ? pr : a[r];
            }
        } else {
            #pragma unroll
            for (int r = 0; r < 4; ++r) {
                if ((r >> PC) & 1) {
                    a[r] = __shfl_xor_sync(0xffffffffu, a[r], MT);
                }
            }
        }
    } else {
        if constexpr (PC >= 2) {
            constexpr int MC = 1 << (PC - 2);
            const bool ctl = (lane & MC) != 0;
            if constexpr (PT == 0) {
                float t0 = a[0], t2 = a[2];
                a[0] = ctl ? a[1] : a[0];  a[1] = ctl ? t0 : a[1];
                a[2] = ctl ? a[3] : a[2];  a[3] = ctl ? t2 : a[3];
            } else {
                float t0 = a[0], t1 = a[1];
                a[0] = ctl ? a[2] : a[0];  a[2] = ctl ? t0 : a[2];
                a[1] = ctl ? a[3] : a[1];  a[3] = ctl ? t1 : a[3];
            }
        } else {
            if constexpr (PC == 1 && PT == 0) { float t = a[2]; a[2] = a[3]; a[3] = t; }
            else                              { float t = a[1]; a[1] = a[3]; a[3] = t; }
        }
    }
}
template<int C, int T>
__device__ __forceinline__ void cnot_w(float a[4], int lane) {
    cnot_p<6 - C, 6 - T>(a, lane);
}
template<int WA, int WB>
__device__ __forceinline__ void conv6(float a[4], int lane,
                                      const float2* __restrict__ cs, int base) {
    #pragma unroll
    for (int q = 0; q < 6; ++q) {
        ry_w<WA>(a, cs[base + 2 * q], lane);
        ry_w<WB>(a, cs[base + 2 * q + 1], lane);
        cnot_w<WA, WB>(a, lane);
    }
}

// ----------------------------- Kernel 1 ------------------------------
// 16 blocks x 256 threads; one warp per basis state (= input index i).
__global__ __launch_bounds__(256) void build_U_kernel(
        const float* __restrict__ QC1, const float* __restrict__ QC2,
        const float* __restrict__ QC3, const float* __restrict__ QP1,
        const float* __restrict__ QP2, const float* __restrict__ QP3,
        const float* __restrict__ QF) {
    __shared__ float2 cs[46];
    const int tid  = threadIdx.x;
    const int lane = tid & 31;
    const int basis = blockIdx.x * 8 + (tid >> 5);

    if (tid < 46) {
        float ang;
        if      (tid < 12) ang = QC1[tid];
        else if (tid < 24) ang = QC2[tid - 12];
        else if (tid < 36) ang = QC3[tid - 24];
        else if (tid == 36) ang =  QP1[0];
        else if (tid == 37) ang =  QP1[1];
        else if (tid == 38) ang = -QP1[1];
        else if (tid == 39) ang =  QP2[0];
        else if (tid == 40) ang =  QP2[1];
        else if (tid == 41) ang = -QP2[1];
        else if (tid == 42) ang =  QP3[0];
        else if (tid == 43) ang =  QP3[1];
        else if (tid == 44) ang = -QP3[1];
        else               ang = QF[0] + QF[1] + QF[2] + QF[3];  // RY angles add
        float sn, c;
        sincosf(0.5f * ang, &sn, &c);
        cs[tid] = make_float2(c, sn);
    }
    __syncthreads();

    float a[4];
    #pragma unroll
    for (int r = 0; r < 4; ++r) a[r] = (lane * 4 + r == basis) ? 1.0f : 0.0f;

    conv6<0,1>(a, lane, cs, 0);  conv6<1,2>(a, lane, cs, 0);
    conv6<2,3>(a, lane, cs, 0);  conv6<3,4>(a, lane, cs, 0);
    conv6<4,5>(a, lane, cs, 0);  conv6<5,6>(a, lane, cs, 0);
    conv6<6,0>(a, lane, cs, 0);
    ry_w<0>(a, cs[36], lane); ry_w<3>(a, cs[37], lane);
    cnot_w<0,3>(a, lane);     ry_w<3>(a, cs[38], lane);
    ry_w<1>(a, cs[36], lane); ry_w<4>(a, cs[37], lane);
    cnot_w<1,4>(a, lane);     ry_w<4>(a, cs[38], lane);
    ry_w<2>(a, cs[36], lane); ry_w<5>(a, cs[37], lane);
    cnot_w<2,5>(a, lane);     ry_w<5>(a, cs[38], lane);
    conv6<3,4>(a, lane, cs, 12);
    conv6<4,5>(a, lane, cs, 12);
    conv6<5,6>(a, lane, cs, 12);
    #pragma unroll
    for (int q = 0; q < 6; ++q) {
        ry_w<6>(a, cs[12 + 2 * q], lane);
        ry_w<3>(a, cs[13 + 2 * q], lane);
        cnot_w<6,0>(a, lane);
    }
    ry_w<3>(a, cs[39], lane); ry_w<5>(a, cs[40], lane);
    cnot_w<3,5>(a, lane);     ry_w<5>(a, cs[41], lane);
    ry_w<4>(a, cs[39], lane); ry_w<6>(a, cs[40], lane);
    cnot_w<4,6>(a, lane);     ry_w<6>(a, cs[41], lane);
    #pragma unroll
    for (int q = 0; q < 6; ++q) {
        ry_w<5>(a, cs[24 + 2 * q], lane);
        ry_w<6>(a, cs[25 + 2 * q], lane);
        cnot_w<4,5>(a, lane);
    }
    ry_w<5>(a, cs[42], lane); ry_w<6>(a, cs[43], lane);
    cnot_w<4,6>(a, lane);     ry_w<6>(a, cs[44], lane);
    ry_w<5>(a, cs[45], lane);
    cnot_w<5,6>(a, lane);
    cnot_w<6,5>(a, lane);

    // a[r] = U[m = lane*4 + r][i = basis]; split to bf16 hi + residual lo.
    #pragma unroll
    for (int r = 0; r < 4; ++r) {
        const int m = lane * 4 + r;
        const __nv_bfloat16 h = __float2bfloat16(a[r]);
        g_Uhi[m * 128 + basis] = h;
        g_Ulo[m * 128 + basis] = __float2bfloat16(a[r] - __bfloat162float(h));
    }
}

// ----------------------------- Kernel 2 ------------------------------
// 128 blocks x 256 threads (8 warps). Block = 32 batches.
// Warp (mi = w>>2, nj = w&3): rows mi*16..+15, cols nj*32..+31
// = 4 m16n8 accum tiles, K = 128 = 8 k16 steps.
// Passes 0+1 fused (share B=Uhi fragments); pass 2 uses Ulo.
// Cross-warp (nj) q-combine via smem, then softmax + float4 store.

#define TCA_THREADS 256
#define TCA_ROWS 32
#define PITCH 272                                // bytes per tile row
#define SM_XHI 0
#define SM_XLO (TCA_ROWS * PITCH)
#define SM_UHI (2 * TCA_ROWS * PITCH)
#define SM_ULO (2 * TCA_ROWS * PITCH + 128 * PITCH)
#define SM_RED (2 * TCA_ROWS * PITCH + 2 * 128 * PITCH)
#define SM_TC_TOTAL (SM_RED + 4 * TCA_ROWS * 16)   // + [4][32] float4

__global__ __launch_bounds__(TCA_THREADS) void qcnn_mma_kernel(
        const float* __restrict__ X, float* __restrict__ out) {
    extern __shared__ char smem[];
    const uint32_t smem_base = smem_to_u32(smem);
    float4* Red = reinterpret_cast<float4*>(smem + SM_RED);  // [nj][32]
    const int tid  = threadIdx.x;
    const int warp = tid >> 5;
    const int lane = tid & 31;

    // --- Stage X tile (32 rows) as bf16 hi/lo into padded smem ---
    const float4* gX4 =
        reinterpret_cast<const float4*>(X + (size_t)blockIdx.x * TCA_ROWS * 128);
    #pragma unroll
    for (int it = 0; it < 4; ++it) {
        const int idx = tid + it * TCA_THREADS;   // 1024 float4 chunks
        const float4 v = gX4[idx];
        const int row = idx >> 5;
        const int col = (idx & 31) << 2;
        const __nv_bfloat16 h0 = __float2bfloat16(v.x);
        const __nv_bfloat16 h1 = __float2bfloat16(v.y);
        const __nv_bfloat16 h2 = __float2bfloat16(v.z);
        const __nv_bfloat16 h3 = __float2bfloat16(v.w);
        const __nv_bfloat16 l0 = __float2bfloat16(v.x - __bfloat162float(h0));
        const __nv_bfloat16 l1 = __float2bfloat16(v.y - __bfloat162float(h1));
        const __nv_bfloat16 l2 = __float2bfloat16(v.z - __bfloat162float(h2));
        const __nv_bfloat16 l3 = __float2bfloat16(v.w - __bfloat162float(h3));
        const int off = row * PITCH + col * 2;
        *reinterpret_cast<uint2*>(smem + SM_XHI + off) =
            make_uint2(pack_bf2(h0, h1), pack_bf2(h2, h3));
        *reinterpret_cast<uint2*>(smem + SM_XLO + off) =
            make_uint2(pack_bf2(l0, l1), pack_bf2(l2, l3));
    }
    // --- Stage U hi/lo (128 rows) with uint4 loads ---
    const uint4* gUh = reinterpret_cast<const uint4*>(g_Uhi);  // 8 bf16/uint4
    const uint4* gUl = reinterpret_cast<const uint4*>(g_Ulo);
    #pragma unroll
    for (int it = 0; it < 8; ++it) {
        const int idx = tid + it * TCA_THREADS;   // 2048 uint4 chunks
        const int row = idx >> 4;
        const int c16 = (idx & 15) * 16;          // byte offset within row
        const int off = row * PITCH + c16;
        *reinterpret_cast<uint4*>(smem + SM_UHI + off) = gUh[idx];
        *reinterpret_cast<uint4*>(smem + SM_ULO + off) = gUl[idx];
    }
    __syncthreads();

    // --- MMA mainloop ---
    const int mi = warp >> 2;                     // row tile 0..1
    const int nj = warp & 3;                      // col quarter 0..3
    const int R0 = mi * 16;
    const int C0 = nj * 32;

    float d[4][4];
    #pragma unroll
    for (int j = 0; j < 4; ++j)
        { d[j][0] = 0.f; d[j][1] = 0.f; d[j][2] = 0.f; d[j][3] = 0.f; }

    const uint32_t aHi = smem_base + SM_XHI
        + (uint32_t)(R0 + (lane & 15)) * PITCH + (uint32_t)(lane >> 4) * 16;
    const uint32_t aLo = smem_base + SM_XLO
        + (uint32_t)(R0 + (lane & 15)) * PITCH + (uint32_t)(lane >> 4) * 16;
    const uint32_t bHi = smem_base + SM_UHI
        + (uint32_t)(C0 + (lane & 7)) * PITCH + (uint32_t)((lane >> 3) & 1) * 16;
    const uint32_t bLo = smem_base + SM_ULO
        + (uint32_t)(C0 + (lane & 7)) * PITCH + (uint32_t)((lane >> 3) & 1) * 16;

    // Fused passes 0+1: Xhi*Uhi + Xlo*Uhi (B fragments loaded once).
    #pragma unroll 1
    for (int ks = 0; ks < 8; ++ks) {
        uint32_t ah[4], al[4];
        ldsm4(ah[0], ah[1], ah[2], ah[3], aHi + ks * 32);
        ldsm4(al[0], al[1], al[2], al[3], aLo + ks * 32);
        const uint32_t bks = bHi + ks * 32;
        #pragma unroll
        for (int j = 0; j < 4; ++j) {
            uint32_t b0, b1;
            ldsm2(b0, b1, bks + j * (8 * PITCH));
            mma_bf16(d[j], ah, b0, b1);
            mma_bf16(d[j], al, b0, b1);
        }
    }
    // Pass 2: Xhi*Ulo.
    #pragma unroll 1
    for (int ks = 0; ks < 8; ++ks) {
        uint32_t ah[4];
        ldsm4(ah[0], ah[1], ah[2], ah[3], aHi + ks * 32);
        const uint32_t bks = bLo + ks * 32;
        #pragma unroll
        for (int j = 0; j < 4; ++j) {
            uint32_t b0, b1;
            ldsm2(b0, b1, bks + j * (8 * PITCH));
            mma_bf16(d[j], ah, b0, b1);
        }
    }

    // --- In-warp q reduction (fragment cols: group parity by lane&1) ---
    float qa0 = 0.f, qa1 = 0.f;   // row r = lane>>2
    float qb0 = 0.f, qb1 = 0.f;   // row r+8
    #pragma unroll
    for (int j = 0; j < 4; ++j) {
        qa0 = fmaf(d[j][0], d[j][0], qa0);
        qa1 = fmaf(d[j][1], d[j][1], qa1);
        qb0 = fmaf(d[j][2], d[j][2], qb0);
        qb1 = fmaf(d[j][3], d[j][3], qb1);
    }
    qa0 += __shfl_xor_sync(0xffffffffu, qa0, 2);
    qa1 += __shfl_xor_sync(0xffffffffu, qa1, 2);
    qb0 += __shfl_xor_sync(0xffffffffu, qb0, 2);
    qb1 += __shfl_xor_sync(0xffffffffu, qb1, 2);
    const float ra0 = __shfl_xor_sync(0xffffffffu, qa0, 1);
    const float ra1 = __shfl_xor_sync(0xffffffffu, qa1, 1);
    const float rb0 = __shfl_xor_sync(0xffffffffu, qb0, 1);
    const float rb1 = __shfl_xor_sync(0xffffffffu, qb1, 1);

    if ((lane & 3) == 0) {
        const int r = lane >> 2;                  // 0..7
        Red[nj * 32 + R0 + r]     = make_float4(qa0, qa1, ra0, ra1);
        Red[nj * 32 + R0 + r + 8] = make_float4(qb0, qb1, rb0, rb1);
    }
    __syncthreads();

    // --- Final combine + softmax: thread t < 32 owns batch row t ---
    if (tid < TCA_ROWS) {
        const float4 u0 = Red[tid];
        const float4 u1 = Red[32 + tid];
        const float4 u2 = Red[64 + tid];
        const float4 u3 = Red[96 + tid];
        const float q0 = (u0.x + u1.x) + (u2.x + u3.x);
        const float q1 = (u0.y + u1.y) + (u2.y + u3.y);
        const float q2 = (u0.z + u1.z) + (u2.z + u3.z);
        const float q3 = (u0.w + u1.w) + (u2.w + u3.w);
        const float S = q0 + q1 + q2 + q3;        // == ||x||^2 (U orthogonal)
        const float inv_s = 1.0f / S;
        const float p0 = q0 * inv_s, p1 = q1 * inv_s;
        const float p2 = q2 * inv_s, p3 = q3 * inv_s;
        const float mx = fmaxf(fmaxf(p0, p1), fmaxf(p2, p3));
        const float e0 = expf(p0 - mx), e1 = expf(p1 - mx);
        const float e2 = expf(p2 - mx), e3 = expf(p3 - mx);
        const float inv = 1.0f / (e0 + e1 + e2 + e3);
        reinterpret_cast<float4*>(out)[blockIdx.x * TCA_ROWS + tid] =
            make_float4(e0 * inv, e1 * inv, e2 * inv, e3 * inv);
    }
}

// ----------------------------- launch --------------------------------
extern "C" void kernel_launch(void* const* d_in, const int* in_sizes, int n_in,
                              void* d_out, int out_size) {
    const float* x   = (const float*)d_in[0];
    const float* QC1 = (const float*)d_in[1];
    const float* QC2 = (const float*)d_in[2];
    const float* QC3 = (const float*)d_in[3];
    const float* QP1 = (const float*)d_in[4];
    const float* QP2 = (const float*)d_in[5];
    const float* QP3 = (const float*)d_in[6];
    const float* QF  = (const float*)d_in[7];

    const int B = in_sizes[0] / 128;

    build_U_kernel<<<16, 256>>>(QC1, QC2, QC3, QP1, QP2, QP3, QF);

    cudaFuncSetAttribute(qcnn_mma_kernel,
                         cudaFuncAttributeMaxDynamicSharedMemorySize,
                         SM_TC_TOTAL);
    qcnn_mma_kernel<<<B / TCA_ROWS, TCA_THREADS, SM_TC_TOTAL>>>(
        x, (float*)d_out);
}

// round 13
// speedup vs baseline: 1.0133x; 1.0133x over previous
#include <cuda_runtime.h>
#include <cuda_bf16.h>
#include <cstdint>

// =====================================================================
// ATQCNN factorization:
//   U = fixed 128x128 orthogonal circuit matrix (wires 0..6; 7,8 inert)
//   Y[b] = U x[b];  q[b,k] = sum_{m&3==k} Y[b,m]^2;  out = softmax(q/sum q)
// Kernel 1: warp-per-basis register simulation -> U as bf16 split
//           (U = U_hi + U_lo residual); coalesced uint4 output stores.
// Kernel 2: mma.sync (m16n8k16 bf16) GEMM. 256 CTAs x 4 warps,
//           CTA = 16 batches; A fragments built from direct global
//           float2 loads (no X smem), U hi/lo staged in smem; per
//           (ks,j): 2 ldsm2 -> 3 mmas (hi*hi + lo*hi + hi*lo).
// =====================================================================

__device__ __align__(16) __nv_bfloat16 g_Uhi[128 * 128];  // [m][i] row-major
__device__ __align__(16) __nv_bfloat16 g_Ulo[128 * 128];  // [m][i] row-major

// --------------------- warp-MMA helpers -------------------------------
__device__ __forceinline__ uint32_t smem_to_u32(const void* p) {
    uint32_t a;
    asm("{ .reg .u64 t; cvta.to.shared.u64 t, %1; cvt.u32.u64 %0, t; }"
        : "=r"(a) : "l"(p));
    return a;
}
__device__ __forceinline__ void ldsm2(uint32_t& r0, uint32_t& r1, uint32_t a) {
    asm volatile("ldmatrix.sync.aligned.m8n8.x2.shared.b16 {%0,%1}, [%2];"
                 : "=r"(r0), "=r"(r1) : "r"(a));
}
__device__ __forceinline__ void mma_bf16(float* d, const uint32_t* a,
                                         uint32_t b0, uint32_t b1) {
    asm volatile(
        "mma.sync.aligned.m16n8k16.row.col.f32.bf16.bf16.f32 "
        "{%0,%1,%2,%3}, {%4,%5,%6,%7}, {%8,%9}, {%0,%1,%2,%3};"
        : "+f"(d[0]), "+f"(d[1]), "+f"(d[2]), "+f"(d[3])
        : "r"(a[0]), "r"(a[1]), "r"(a[2]), "r"(a[3]), "r"(b0), "r"(b1));
}
__device__ __forceinline__ uint32_t pack_bf2(__nv_bfloat16 a, __nv_bfloat16 b) {
    __nv_bfloat162 t = __halves2bfloat162(a, b);
    return *reinterpret_cast<uint32_t*>(&t);
}

// --------------------- gate primitives (register sim) -----------------
template<int P>
__device__ __forceinline__ void ry_p(float a[4], float c, float s, int lane) {
    if constexpr (P == 0) {
        float n0 = c * a[0] - s * a[1];
        float n1 = fmaf(s, a[0], c * a[1]);
        float n2 = c * a[2] - s * a[3];
        float n3 = fmaf(s, a[2], c * a[3]);
        a[0] = n0; a[1] = n1; a[2] = n2; a[3] = n3;
    } else if constexpr (P == 1) {
        float n0 = c * a[0] - s * a[2];
        float n2 = fmaf(s, a[0], c * a[2]);
        float n1 = c * a[1] - s * a[3];
        float n3 = fmaf(s, a[1], c * a[3]);
        a[0] = n0; a[1] = n1; a[2] = n2; a[3] = n3;
    } else {
        constexpr int M = 1 << (P - 2);
        const float sgn = (lane & M) ? s : -s;
        #pragma unroll
        for (int r = 0; r < 4; ++r) {
            float pr = __shfl_xor_sync(0xffffffffu, a[r], M);
            a[r] = fmaf(sgn, pr, c * a[r]);
        }
    }
}
template<int W>
__device__ __forceinline__ void ry_w(float a[4], float2 cs, int lane) {
    ry_p<6 - W>(a, cs.x, cs.y, lane);
}
template<int PC, int PT>
__device__ __forceinline__ void cnot_p(float a[4], int lane) {
    if constexpr (PT >= 2) {
        constexpr int MT = 1 << (PT - 2);
        if constexpr (PC >= 2) {
            constexpr int MC = 1 << (PC - 2);
            const bool ctl = (lane & MC) != 0;
            #pragma unroll
            for (int r = 0; r < 4; ++r) {
                float pr = __shfl_xor_sync(0xffffffffu, a[r], MT);
                a[r] = ctl ? pr : a[r];
            }
        } else {
            #pragma unroll
            for (int r = 0; r < 4; ++r) {
                if ((r >> PC) & 1) {
                    a[r] = __shfl_xor_sync(0xffffffffu, a[r], MT);
                }
            }
        }
    } else {
        if constexpr (PC >= 2) {
            constexpr int MC = 1 << (PC - 2);
            const bool ctl = (lane & MC) != 0;
            if constexpr (PT == 0) {
                float t0 = a[0], t2 = a[2];
                a[0] = ctl ? a[1] : a[0];  a[1] = ctl ? t0 : a[1];
                a[2] = ctl ? a[3] : a[2];  a[3] = ctl ? t2 : a[3];
            } else {
                float t0 = a[0], t1 = a[1];
                a[0] = ctl ? a[2] : a[0];  a[2] = ctl ? t0 : a[2];
                a[1] = ctl ? a[3] : a[1];  a[3] = ctl ? t1 : a[3];
            }
        } else {
            if constexpr (PC == 1 && PT == 0) { float t = a[2]; a[2] = a[3]; a[3] = t; }
            else                              { float t = a[1]; a[1] = a[3]; a[3] = t; }
        }
    }
}
template<int C, int T>
__device__ __forceinline__ void cnot_w(float a[4], int lane) {
    cnot_p<6 - C, 6 - T>(a, lane);
}
template<int WA, int WB>
__device__ __forceinline__ void conv6(float a[4], int lane,
                                      const float2* __restrict__ cs, int base) {
    #pragma unroll
    for (int q = 0; q < 6; ++q) {
        ry_w<WA>(a, cs[base + 2 * q], lane);
        ry_w<WB>(a, cs[base + 2 * q + 1], lane);
        cnot_w<WA, WB>(a, lane);
    }
}

// ----------------------------- Kernel 1 ------------------------------
// 16 blocks x 256 threads; one warp per basis state (= input index i).
// Output transposed through smem -> one uint4 store per (m, array).
__global__ __launch_bounds__(256) void build_U_kernel(
        const float* __restrict__ QC1, const float* __restrict__ QC2,
        const float* __restrict__ QC3, const float* __restrict__ QP1,
        const float* __restrict__ QP2, const float* __restrict__ QP3,
        const float* __restrict__ QF) {
    __shared__ float2 cs[46];
    __shared__ __align__(16) __nv_bfloat16 sh[128][8];
    __shared__ __align__(16) __nv_bfloat16 sl[128][8];
    const int tid  = threadIdx.x;
    const int lane = tid & 31;
    const int wid  = tid >> 5;
    const int basis = blockIdx.x * 8 + wid;

    if (tid < 46) {
        float ang;
        if      (tid < 12) ang = QC1[tid];
        else if (tid < 24) ang = QC2[tid - 12];
        else if (tid < 36) ang = QC3[tid - 24];
        else if (tid == 36) ang =  QP1[0];
        else if (tid == 37) ang =  QP1[1];
        else if (tid == 38) ang = -QP1[1];
        else if (tid == 39) ang =  QP2[0];
        else if (tid == 40) ang =  QP2[1];
        else if (tid == 41) ang = -QP2[1];
        else if (tid == 42) ang =  QP3[0];
        else if (tid == 43) ang =  QP3[1];
        else if (tid == 44) ang = -QP3[1];
        else               ang = QF[0] + QF[1] + QF[2] + QF[3];  // RY angles add
        float sn, c;
        sincosf(0.5f * ang, &sn, &c);
        cs[tid] = make_float2(c, sn);
    }
    __syncthreads();

    float a[4];
    #pragma unroll
    for (int r = 0; r < 4; ++r) a[r] = (lane * 4 + r == basis) ? 1.0f : 0.0f;

    conv6<0,1>(a, lane, cs, 0);  conv6<1,2>(a, lane, cs, 0);
    conv6<2,3>(a, lane, cs, 0);  conv6<3,4>(a, lane, cs, 0);
    conv6<4,5>(a, lane, cs, 0);  conv6<5,6>(a, lane, cs, 0);
    conv6<6,0>(a, lane, cs, 0);
    ry_w<0>(a, cs[36], lane); ry_w<3>(a, cs[37], lane);
    cnot_w<0,3>(a, lane);     ry_w<3>(a, cs[38], lane);
    ry_w<1>(a, cs[36], lane); ry_w<4>(a, cs[37], lane);
    cnot_w<1,4>(a, lane);     ry_w<4>(a, cs[38], lane);
    ry_w<2>(a, cs[36], lane); ry_w<5>(a, cs[37], lane);
    cnot_w<2,5>(a, lane);     ry_w<5>(a, cs[38], lane);
    conv6<3,4>(a, lane, cs, 12);
    conv6<4,5>(a, lane, cs, 12);
    conv6<5,6>(a, lane, cs, 12);
    #pragma unroll
    for (int q = 0; q < 6; ++q) {
        ry_w<6>(a, cs[12 + 2 * q], lane);
        ry_w<3>(a, cs[13 + 2 * q], lane);
        cnot_w<6,0>(a, lane);
    }
    ry_w<3>(a, cs[39], lane); ry_w<5>(a, cs[40], lane);
    cnot_w<3,5>(a, lane);     ry_w<5>(a, cs[41], lane);
    ry_w<4>(a, cs[39], lane); ry_w<6>(a, cs[40], lane);
    cnot_w<4,6>(a, lane);     ry_w<6>(a, cs[41], lane);
    #pragma unroll
    for (int q = 0; q < 6; ++q) {
        ry_w<5>(a, cs[24 + 2 * q], lane);
        ry_w<6>(a, cs[25 + 2 * q], lane);
        cnot_w<4,5>(a, lane);
    }
    ry_w<5>(a, cs[42], lane); ry_w<6>(a, cs[43], lane);
    cnot_w<4,6>(a, lane);     ry_w<6>(a, cs[44], lane);
    ry_w<5>(a, cs[45], lane);
    cnot_w<5,6>(a, lane);
    cnot_w<6,5>(a, lane);

    // a[r] = U[m = lane*4 + r][i = basis]; split and transpose in smem.
    #pragma unroll
    for (int r = 0; r < 4; ++r) {
        const int m = lane * 4 + r;
        const __nv_bfloat16 h = __float2bfloat16(a[r]);
        sh[m][wid] = h;
        sl[m][wid] = __float2bfloat16(a[r] - __bfloat162float(h));
    }
    __syncthreads();

    // Coalesced-ish stores: one uint4 (8 bf16 = this block's 8 columns).
    if (tid < 128) {
        *reinterpret_cast<uint4*>(&g_Uhi[tid * 128 + blockIdx.x * 8]) =
            *reinterpret_cast<const uint4*>(&sh[tid][0]);
    } else {
        const int m = tid - 128;
        *reinterpret_cast<uint4*>(&g_Ulo[m * 128 + blockIdx.x * 8]) =
            *reinterpret_cast<const uint4*>(&sl[m][0]);
    }
}

// ----------------------------- Kernel 2 ------------------------------
// 256 blocks x 128 threads (4 warps). Block = 16 batches.
// Warp nj: rows 0..15, cols nj*32..+31 = 4 m16n8 tiles, 8 k16 steps.
// A fragments built from direct global float2 loads (hi/lo split in
// registers, per the m16n8k16 A layout). Per (ks,j): ldsm2 Bhi + ldsm2
// Blo feed 3 mmas (ah*bh, al*bh, ah*bl). q-combine via smem + softmax.

#define TCA_THREADS 128
#define TCA_ROWS 16
#define PITCH 272                                // bytes per U tile row
#define SM_UHI 0
#define SM_ULO (128 * PITCH)
#define SM_RED (2 * 128 * PITCH)
#define SM_TC_TOTAL (SM_RED + 4 * TCA_ROWS * 16)   // + [4][16] float4

__global__ __launch_bounds__(TCA_THREADS) void qcnn_mma_kernel(
        const float* __restrict__ X, float* __restrict__ out) {
    extern __shared__ char smem[];
    const uint32_t smem_base = smem_to_u32(smem);
    float4* Red = reinterpret_cast<float4*>(smem + SM_RED);  // [nj][16]
    const int tid  = threadIdx.x;
    const int warp = tid >> 5;
    const int lane = tid & 31;

    // --- Stage U hi/lo (128 rows x 128 bf16) with uint4 loads ---
    const uint4* gUh = reinterpret_cast<const uint4*>(g_Uhi);  // 8 bf16/uint4
    const uint4* gUl = reinterpret_cast<const uint4*>(g_Ulo);
    #pragma unroll
    for (int it = 0; it < 16; ++it) {
        const int idx = tid + it * TCA_THREADS;   // 2048 uint4 chunks
        const int row = idx >> 4;
        const int c16 = (idx & 15) * 16;
        const int off = row * PITCH + c16;
        *reinterpret_cast<uint4*>(smem + SM_UHI + off) = gUh[idx];
        *reinterpret_cast<uint4*>(smem + SM_ULO + off) = gUl[idx];
    }
    __syncthreads();

    // --- MMA mainloop ---
    const int nj = warp;                          // col quarter 0..3
    const int C0 = nj * 32;
    const int r  = lane >> 2;                     // A row in group (0..7)
    const int c2 = (lane & 3) * 2;                // A k-offset in group

    float d[4][4];
    #pragma unroll
    for (int j = 0; j < 4; ++j)
        { d[j][0] = 0.f; d[j][1] = 0.f; d[j][2] = 0.f; d[j][3] = 0.f; }

    const float* Xb = X + (size_t)blockIdx.x * TCA_ROWS * 128;
    const uint32_t bHi = smem_base + SM_UHI
        + (uint32_t)(C0 + (lane & 7)) * PITCH + (uint32_t)((lane >> 3) & 1) * 16;
    const uint32_t bLo = smem_base + SM_ULO
        + (uint32_t)(C0 + (lane & 7)) * PITCH + (uint32_t)((lane >> 3) & 1) * 16;

    #pragma unroll 1
    for (int ks = 0; ks < 8; ++ks) {
        // Build A fragments (hi/lo) from global X.
        // reg f: row = r + 8*(f&1), k = ks*16 + c2 + 8*(f>>1)
        uint32_t ah[4], al[4];
        #pragma unroll
        for (int f = 0; f < 4; ++f) {
            const int ro = (f & 1) * 8;
            const int ko = (f >> 1) * 8;
            const float2 v = *reinterpret_cast<const float2*>(
                Xb + (r + ro) * 128 + ks * 16 + c2 + ko);
            const __nv_bfloat16 h0 = __float2bfloat16(v.x);
            const __nv_bfloat16 h1 = __float2bfloat16(v.y);
            ah[f] = pack_bf2(h0, h1);
            al[f] = pack_bf2(__float2bfloat16(v.x - __bfloat162float(h0)),
                             __float2bfloat16(v.y - __bfloat162float(h1)));
        }
        const uint32_t bksH = bHi + ks * 32;
        const uint32_t bksL = bLo + ks * 32;
        #pragma unroll
        for (int j = 0; j < 4; ++j) {
            uint32_t bh0, bh1, bl0, bl1;
            ldsm2(bh0, bh1, bksH + j * (8 * PITCH));
            ldsm2(bl0, bl1, bksL + j * (8 * PITCH));
            mma_bf16(d[j], ah, bh0, bh1);
            mma_bf16(d[j], al, bh0, bh1);
            mma_bf16(d[j], ah, bl0, bl1);
        }
    }

    // --- In-warp q reduction (fragment cols: group parity by lane&1) ---
    float qa0 = 0.f, qa1 = 0.f;   // row r
    float qb0 = 0.f, qb1 = 0.f;   // row r+8
    #pragma unroll
    for (int j = 0; j < 4; ++j) {
        qa0 = fmaf(d[j][0], d[j][0], qa0);
        qa1 = fmaf(d[j][1], d[j][1], qa1);
        qb0 = fmaf(d[j][2], d[j][2], qb0);
        qb1 = fmaf(d[j][3], d[j][3], qb1);
    }
    qa0 += __shfl_xor_sync(0xffffffffu, qa0, 2);
    qa1 += __shfl_xor_sync(0xffffffffu, qa1, 2);
    qb0 += __shfl_xor_sync(0xffffffffu, qb0, 2);
    qb1 += __shfl_xor_sync(0xffffffffu, qb1, 2);
    const float ra0 = __shfl_xor_sync(0xffffffffu, qa0, 1);
    const float ra1 = __shfl_xor_sync(0xffffffffu, qa1, 1);
    const float rb0 = __shfl_xor_sync(0xffffffffu, qb0, 1);
    const float rb1 = __shfl_xor_sync(0xffffffffu, qb1, 1);

    if ((lane & 3) == 0) {
        Red[nj * 16 + r]     = make_float4(qa0, qa1, ra0, ra1);
        Red[nj * 16 + r + 8] = make_float4(qb0, qb1, rb0, rb1);
    }
    __syncthreads();

    // --- Final combine + softmax: thread t < 16 owns batch row t ---
    if (tid < TCA_ROWS) {
        const float4 u0 = Red[tid];
        const float4 u1 = Red[16 + tid];
        const float4 u2 = Red[32 + tid];
        const float4 u3 = Red[48 + tid];
        const float q0 = (u0.x + u1.x) + (u2.x + u3.x);
        const float q1 = (u0.y + u1.y) + (u2.y + u3.y);
        const float q2 = (u0.z + u1.z) + (u2.z + u3.z);
        const float q3 = (u0.w + u1.w) + (u2.w + u3.w);
        const float S = q0 + q1 + q2 + q3;        // == ||x||^2 (U orthogonal)
        const float inv_s = 1.0f / S;
        const float p0 = q0 * inv_s, p1 = q1 * inv_s;
        const float p2 = q2 * inv_s, p3 = q3 * inv_s;
        const float mx = fmaxf(fmaxf(p0, p1), fmaxf(p2, p3));
        const float e0 = expf(p0 - mx), e1 = expf(p1 - mx);
        const float e2 = expf(p2 - mx), e3 = expf(p3 - mx);
        const float inv = 1.0f / (e0 + e1 + e2 + e3);
        reinterpret_cast<float4*>(out)[blockIdx.x * TCA_ROWS + tid] =
            make_float4(e0 * inv, e1 * inv, e2 * inv, e3 * inv);
    }
}

// ----------------------------- launch --------------------------------
extern "C" void kernel_launch(void* const* d_in, const int* in_sizes, int n_in,
                              void* d_out, int out_size) {
    const float* x   = (const float*)d_in[0];
    const float* QC1 = (const float*)d_in[1];
    const float* QC2 = (const float*)d_in[2];
    const float* QC3 = (const float*)d_in[3];
    const float* QP1 = (const float*)d_in[4];
    const float* QP2 = (const float*)d_in[5];
    const float* QP3 = (const float*)d_in[6];
    const float* QF  = (const float*)d_in[7];

    const int B = in_sizes[0] / 128;

    build_U_kernel<<<16, 256>>>(QC1, QC2, QC3, QP1, QP2, QP3, QF);

    cudaFuncSetAttribute(qcnn_mma_kernel,
                         cudaFuncAttributeMaxDynamicSharedMemorySize,
                         SM_TC_TOTAL);
    qcnn_mma_kernel<<<B / TCA_ROWS, TCA_THREADS, SM_TC_TOTAL>>>(
        x, (float*)d_out);
}

// round 14
// speedup vs baseline: 1.0616x; 1.0477x over previous
#include <cuda_runtime.h>
#include <cuda_bf16.h>
#include <cstdint>

// =====================================================================
// ATQCNN factorization:
//   U = fixed 128x128 orthogonal circuit matrix (wires 0..6; 7,8 inert)
//   Y[b] = U x[b];  q[b,k] = sum_{m&3==k} Y[b,m]^2;  out = softmax(q/sum q)
// Kernel 1 (R13 version): warp-per-basis register sim -> U bf16 split,
//   smem-transposed coalesced uint4 stores.
// Kernel 2 (R11 version): mma.sync m16n8k16 bf16 GEMM, 3 accumulated
//   passes (Xhi·Uhi + Xlo·Uhi + Xhi·Ulo), 128 CTAs x 4 warps (2m x 2n),
//   B fragments shared across hi/lo passes, smem q-combine + softmax.
// =====================================================================

__device__ __align__(16) __nv_bfloat16 g_Uhi[128 * 128];  // [m][i] row-major
__device__ __align__(16) __nv_bfloat16 g_Ulo[128 * 128];  // [m][i] row-major

// --------------------- warp-MMA helpers -------------------------------
__device__ __forceinline__ uint32_t smem_to_u32(const void* p) {
    uint32_t a;
    asm("{ .reg .u64 t; cvta.to.shared.u64 t, %1; cvt.u32.u64 %0, t; }"
        : "=r"(a) : "l"(p));
    return a;
}
__device__ __forceinline__ void ldsm4(uint32_t& r0, uint32_t& r1,
                                      uint32_t& r2, uint32_t& r3, uint32_t a) {
    asm volatile("ldmatrix.sync.aligned.m8n8.x4.shared.b16 {%0,%1,%2,%3}, [%4];"
                 : "=r"(r0), "=r"(r1), "=r"(r2), "=r"(r3) : "r"(a));
}
__device__ __forceinline__ void ldsm2(uint32_t& r0, uint32_t& r1, uint32_t a) {
    asm volatile("ldmatrix.sync.aligned.m8n8.x2.shared.b16 {%0,%1}, [%2];"
                 : "=r"(r0), "=r"(r1) : "r"(a));
}
__device__ __forceinline__ void mma_bf16(float* d, const uint32_t* a,
                                         uint32_t b0, uint32_t b1) {
    asm volatile(
        "mma.sync.aligned.m16n8k16.row.col.f32.bf16.bf16.f32 "
        "{%0,%1,%2,%3}, {%4,%5,%6,%7}, {%8,%9}, {%0,%1,%2,%3};"
        : "+f"(d[0]), "+f"(d[1]), "+f"(d[2]), "+f"(d[3])
        : "r"(a[0]), "r"(a[1]), "r"(a[2]), "r"(a[3]), "r"(b0), "r"(b1));
}
__device__ __forceinline__ uint32_t pack_bf2(__nv_bfloat16 a, __nv_bfloat16 b) {
    __nv_bfloat162 t = __halves2bfloat162(a, b);
    return *reinterpret_cast<uint32_t*>(&t);
}

// --------------------- gate primitives (register sim) -----------------
template<int P>
__device__ __forceinline__ void ry_p(float a[4], float c, float s, int lane) {
    if constexpr (P == 0) {
        float n0 = c * a[0] - s * a[1];
        float n1 = fmaf(s, a[0], c * a[1]);
        float n2 = c * a[2] - s * a[3];
        float n3 = fmaf(s, a[2], c * a[3]);
        a[0] = n0; a[1] = n1; a[2] = n2; a[3] = n3;
    } else if constexpr (P == 1) {
        float n0 = c * a[0] - s * a[2];
        float n2 = fmaf(s, a[0], c * a[2]);
        float n1 = c * a[1] - s * a[3];
        float n3 = fmaf(s, a[1], c * a[3]);
        a[0] = n0; a[1] = n1; a[2] = n2; a[3] = n3;
    } else {
        constexpr int M = 1 << (P - 2);
        const float sgn = (lane & M) ? s : -s;
        #pragma unroll
        for (int r = 0; r < 4; ++r) {
            float pr = __shfl_xor_sync(0xffffffffu, a[r], M);
            a[r] = fmaf(sgn, pr, c * a[r]);
        }
    }
}
template<int W>
__device__ __forceinline__ void ry_w(float a[4], float2 cs, int lane) {
    ry_p<6 - W>(a, cs.x, cs.y, lane);
}
template<int PC, int PT>
__device__ __forceinline__ void cnot_p(float a[4], int lane) {
    if constexpr (PT >= 2) {
        constexpr int MT = 1 << (PT - 2);
        if constexpr (PC >= 2) {
            constexpr int MC = 1 << (PC - 2);
            const bool ctl = (lane & MC) != 0;
            #pragma unroll
            for (int r = 0; r < 4; ++r) {
                float pr = __shfl_xor_sync(0xffffffffu, a[r], MT);
                a[r] = ctl ? pr : a[r];
            }
        } else {
            #pragma unroll
            for (int r = 0; r < 4; ++r) {
                if ((r >> PC) & 1) {
                    a[r] = __shfl_xor_sync(0xffffffffu, a[r], MT);
                }
            }
        }
    } else {
        if constexpr (PC >= 2) {
            constexpr int MC = 1 << (PC - 2);
            const bool ctl = (lane & MC) != 0;
            if constexpr (PT == 0) {
                float t0 = a[0], t2 = a[2];
                a[0] = ctl ? a[1] : a[0];  a[1] = ctl ? t0 : a[1];
                a[2] = ctl ? a[3] : a[2];  a[3] = ctl ? t2 : a[3];
            } else {
                float t0 = a[0], t1 = a[1];
                a[0] = ctl ? a[2] : a[0];  a[2] = ctl ? t0 : a[2];
                a[1] = ctl ? a[3] : a[1];  a[3] = ctl ? t1 : a[3];
            }
        } else {
            if constexpr (PC == 1 && PT == 0) { float t = a[2]; a[2] = a[3]; a[3] = t; }
            else                              { float t = a[1]; a[1] = a[3]; a[3] = t; }
        }
    }
}
template<int C, int T>
__device__ __forceinline__ void cnot_w(float a[4], int lane) {
    cnot_p<6 - C, 6 - T>(a, lane);
}
template<int WA, int WB>
__device__ __forceinline__ void conv6(float a[4], int lane,
                                      const float2* __restrict__ cs, int base) {
    #pragma unroll
    for (int q = 0; q < 6; ++q) {
        ry_w<WA>(a, cs[base + 2 * q], lane);
        ry_w<WB>(a, cs[base + 2 * q + 1], lane);
        cnot_w<WA, WB>(a, lane);
    }
}

// ----------------------------- Kernel 1 ------------------------------
// 16 blocks x 256 threads; one warp per basis state (= input index i).
// Output transposed through smem -> one uint4 store per (m, array).
__global__ __launch_bounds__(256) void build_U_kernel(
        const float* __restrict__ QC1, const float* __restrict__ QC2,
        const float* __restrict__ QC3, const float* __restrict__ QP1,
        const float* __restrict__ QP2, const float* __restrict__ QP3,
        const float* __restrict__ QF) {
    __shared__ float2 cs[46];
    __shared__ __align__(16) __nv_bfloat16 sh[128][8];
    __shared__ __align__(16) __nv_bfloat16 sl[128][8];
    const int tid  = threadIdx.x;
    const int lane = tid & 31;
    const int wid  = tid >> 5;
    const int basis = blockIdx.x * 8 + wid;

    if (tid < 46) {
        float ang;
        if      (tid < 12) ang = QC1[tid];
        else if (tid < 24) ang = QC2[tid - 12];
        else if (tid < 36) ang = QC3[tid - 24];
        else if (tid == 36) ang =  QP1[0];
        else if (tid == 37) ang =  QP1[1];
        else if (tid == 38) ang = -QP1[1];
        else if (tid == 39) ang =  QP2[0];
        else if (tid == 40) ang =  QP2[1];
        else if (tid == 41) ang = -QP2[1];
        else if (tid == 42) ang =  QP3[0];
        else if (tid == 43) ang =  QP3[1];
        else if (tid == 44) ang = -QP3[1];
        else               ang = QF[0] + QF[1] + QF[2] + QF[3];  // RY angles add
        float sn, c;
        sincosf(0.5f * ang, &sn, &c);
        cs[tid] = make_float2(c, sn);
    }
    __syncthreads();

    float a[4];
    #pragma unroll
    for (int r = 0; r < 4; ++r) a[r] = (lane * 4 + r == basis) ? 1.0f : 0.0f;

    conv6<0,1>(a, lane, cs, 0);  conv6<1,2>(a, lane, cs, 0);
    conv6<2,3>(a, lane, cs, 0);  conv6<3,4>(a, lane, cs, 0);
    conv6<4,5>(a, lane, cs, 0);  conv6<5,6>(a, lane, cs, 0);
    conv6<6,0>(a, lane, cs, 0);
    ry_w<0>(a, cs[36], lane); ry_w<3>(a, cs[37], lane);
    cnot_w<0,3>(a, lane);     ry_w<3>(a, cs[38], lane);
    ry_w<1>(a, cs[36], lane); ry_w<4>(a, cs[37], lane);
    cnot_w<1,4>(a, lane);     ry_w<4>(a, cs[38], lane);
    ry_w<2>(a, cs[36], lane); ry_w<5>(a, cs[37], lane);
    cnot_w<2,5>(a, lane);     ry_w<5>(a, cs[38], lane);
    conv6<3,4>(a, lane, cs, 12);
    conv6<4,5>(a, lane, cs, 12);
    conv6<5,6>(a, lane, cs, 12);
    #pragma unroll
    for (int q = 0; q < 6; ++q) {
        ry_w<6>(a, cs[12 + 2 * q], lane);
        ry_w<3>(a, cs[13 + 2 * q], lane);
        cnot_w<6,0>(a, lane);
    }
    ry_w<3>(a, cs[39], lane); ry_w<5>(a, cs[40], lane);
    cnot_w<3,5>(a, lane);     ry_w<5>(a, cs[41], lane);
    ry_w<4>(a, cs[39], lane); ry_w<6>(a, cs[40], lane);
    cnot_w<4,6>(a, lane);     ry_w<6>(a, cs[41], lane);
    #pragma unroll
    for (int q = 0; q < 6; ++q) {
        ry_w<5>(a, cs[24 + 2 * q], lane);
        ry_w<6>(a, cs[25 + 2 * q], lane);
        cnot_w<4,5>(a, lane);
    }
    ry_w<5>(a, cs[42], lane); ry_w<6>(a, cs[43], lane);
    cnot_w<4,6>(a, lane);     ry_w<6>(a, cs[44], lane);
    ry_w<5>(a, cs[45], lane);
    cnot_w<5,6>(a, lane);
    cnot_w<6,5>(a, lane);

    // a[r] = U[m = lane*4 + r][i = basis]; split and transpose in smem.
    #pragma unroll
    for (int r = 0; r < 4; ++r) {
        const int m = lane * 4 + r;
        const __nv_bfloat16 h = __float2bfloat16(a[r]);
        sh[m][wid] = h;
        sl[m][wid] = __float2bfloat16(a[r] - __bfloat162float(h));
    }
    __syncthreads();

    // Coalesced-ish stores: one uint4 (8 bf16 = this block's 8 columns).
    if (tid < 128) {
        *reinterpret_cast<uint4*>(&g_Uhi[tid * 128 + blockIdx.x * 8]) =
            *reinterpret_cast<const uint4*>(&sh[tid][0]);
    } else {
        const int m = tid - 128;
        *reinterpret_cast<uint4*>(&g_Ulo[m * 128 + blockIdx.x * 8]) =
            *reinterpret_cast<const uint4*>(&sl[m][0]);
    }
}

// ----------------------------- Kernel 2 ------------------------------
// 128 blocks x 128 threads (4 warps). Block = 32 batches.
// Warp (mi = w>>1, nj = w&1): rows mi*16..+15, cols nj*64..+63
// = 8 m16n8 accum tiles, K = 128 = 8 k16 steps.
// Passes 0+1 fused (share B=Uhi fragments); pass 2 uses Ulo.
// Cross-warp (nj) q-combine via smem, then softmax + float4 store.

#define TCA_THREADS 128
#define TCA_ROWS 32
#define PITCH 272                                // bytes per tile row
#define SM_XHI 0
#define SM_XLO (TCA_ROWS * PITCH)
#define SM_UHI (2 * TCA_ROWS * PITCH)
#define SM_ULO (2 * TCA_ROWS * PITCH + 128 * PITCH)
#define SM_RED (2 * TCA_ROWS * PITCH + 2 * 128 * PITCH)
#define SM_TC_TOTAL (SM_RED + 2 * TCA_ROWS * 16)   // + [2][32] float4

__global__ __launch_bounds__(TCA_THREADS) void qcnn_mma_kernel(
        const float* __restrict__ X, float* __restrict__ out) {
    extern __shared__ char smem[];
    const uint32_t smem_base = smem_to_u32(smem);
    float4* Red = reinterpret_cast<float4*>(smem + SM_RED);  // [nj][32]
    const int tid  = threadIdx.x;
    const int warp = tid >> 5;
    const int lane = tid & 31;

    // --- Stage X tile (32 rows) as bf16 hi/lo into padded smem ---
    const float4* gX4 =
        reinterpret_cast<const float4*>(X + (size_t)blockIdx.x * TCA_ROWS * 128);
    #pragma unroll
    for (int it = 0; it < 8; ++it) {
        const int idx = tid + it * TCA_THREADS;   // 1024 float4 chunks
        const float4 v = gX4[idx];
        const int row = idx >> 5;
        const int col = (idx & 31) << 2;
        const __nv_bfloat16 h0 = __float2bfloat16(v.x);
        const __nv_bfloat16 h1 = __float2bfloat16(v.y);
        const __nv_bfloat16 h2 = __float2bfloat16(v.z);
        const __nv_bfloat16 h3 = __float2bfloat16(v.w);
        const __nv_bfloat16 l0 = __float2bfloat16(v.x - __bfloat162float(h0));
        const __nv_bfloat16 l1 = __float2bfloat16(v.y - __bfloat162float(h1));
        const __nv_bfloat16 l2 = __float2bfloat16(v.z - __bfloat162float(h2));
        const __nv_bfloat16 l3 = __float2bfloat16(v.w - __bfloat162float(h3));
        const int off = row * PITCH + col * 2;
        *reinterpret_cast<uint2*>(smem + SM_XHI + off) =
            make_uint2(pack_bf2(h0, h1), pack_bf2(h2, h3));
        *reinterpret_cast<uint2*>(smem + SM_XLO + off) =
            make_uint2(pack_bf2(l0, l1), pack_bf2(l2, l3));
    }
    // --- Stage U hi/lo (128 rows) with uint4 loads ---
    const uint4* gUh = reinterpret_cast<const uint4*>(g_Uhi);  // 8 bf16/uint4
    const uint4* gUl = reinterpret_cast<const uint4*>(g_Ulo);
    #pragma unroll
    for (int it = 0; it < 16; ++it) {
        const int idx = tid + it * TCA_THREADS;   // 2048 uint4 chunks
        const int row = idx >> 4;
        const int c16 = (idx & 15) * 16;          // byte offset within row
        const int off = row * PITCH + c16;
        *reinterpret_cast<uint4*>(smem + SM_UHI + off) = gUh[idx];
        *reinterpret_cast<uint4*>(smem + SM_ULO + off) = gUl[idx];
    }
    __syncthreads();

    // --- MMA mainloop ---
    const int mi = warp >> 1;                     // row tile 0..1
    const int nj = warp & 1;                      // col half 0..1
    const int R0 = mi * 16;
    const int C0 = nj * 64;

    float d[8][4];
    #pragma unroll
    for (int j = 0; j < 8; ++j)
        { d[j][0] = 0.f; d[j][1] = 0.f; d[j][2] = 0.f; d[j][3] = 0.f; }

    const uint32_t aHi = smem_base + SM_XHI
        + (uint32_t)(R0 + (lane & 15)) * PITCH + (uint32_t)(lane >> 4) * 16;
    const uint32_t aLo = smem_base + SM_XLO
        + (uint32_t)(R0 + (lane & 15)) * PITCH + (uint32_t)(lane >> 4) * 16;
    const uint32_t bHi = smem_base + SM_UHI
        + (uint32_t)(C0 + (lane & 7)) * PITCH + (uint32_t)((lane >> 3) & 1) * 16;
    const uint32_t bLo = smem_base + SM_ULO
        + (uint32_t)(C0 + (lane & 7)) * PITCH + (uint32_t)((lane >> 3) & 1) * 16;

    // Fused passes 0+1: Xhi*Uhi + Xlo*Uhi (B fragments loaded once).
    #pragma unroll 1
    for (int ks = 0; ks < 8; ++ks) {
        uint32_t ah[4], al[4];
        ldsm4(ah[0], ah[1], ah[2], ah[3], aHi + ks * 32);
        ldsm4(al[0], al[1], al[2], al[3], aLo + ks * 32);
        const uint32_t bks = bHi + ks * 32;
        #pragma unroll
        for (int j = 0; j < 8; ++j) {
            uint32_t b0, b1;
            ldsm2(b0, b1, bks + j * (8 * PITCH));
            mma_bf16(d[j], ah, b0, b1);
            mma_bf16(d[j], al, b0, b1);
        }
    }
    // Pass 2: Xhi*Ulo.
    #pragma unroll 1
    for (int ks = 0; ks < 8; ++ks) {
        uint32_t ah[4];
        ldsm4(ah[0], ah[1], ah[2], ah[3], aHi + ks * 32);
        const uint32_t bks = bLo + ks * 32;
        #pragma unroll
        for (int j = 0; j < 8; ++j) {
            uint32_t b0, b1;
            ldsm2(b0, b1, bks + j * (8 * PITCH));
            mma_bf16(d[j], ah, b0, b1);
        }
    }

    // --- In-warp q reduction (fragment cols: group parity by lane&1) ---
    float qa0 = 0.f, qa1 = 0.f;   // row r = lane>>2
    float qb0 = 0.f, qb1 = 0.f;   // row r+8
    #pragma unroll
    for (int j = 0; j < 8; ++j) {
        qa0 = fmaf(d[j][0], d[j][0], qa0);
        qa1 = fmaf(d[j][1], d[j][1], qa1);
        qb0 = fmaf(d[j][2], d[j][2], qb0);
        qb1 = fmaf(d[j][3], d[j][3], qb1);
    }
    qa0 += __shfl_xor_sync(0xffffffffu, qa0, 2);
    qa1 += __shfl_xor_sync(0xffffffffu, qa1, 2);
    qb0 += __shfl_xor_sync(0xffffffffu, qb0, 2);
    qb1 += __shfl_xor_sync(0xffffffffu, qb1, 2);
    const float ra0 = __shfl_xor_sync(0xffffffffu, qa0, 1);
    const float ra1 = __shfl_xor_sync(0xffffffffu, qa1, 1);
    const float rb0 = __shfl_xor_sync(0xffffffffu, qb0, 1);
    const float rb1 = __shfl_xor_sync(0xffffffffu, qb1, 1);

    if ((lane & 3) == 0) {
        const int r = lane >> 2;                  // 0..7
        Red[nj * 32 + R0 + r]     = make_float4(qa0, qa1, ra0, ra1);
        Red[nj * 32 + R0 + r + 8] = make_float4(qb0, qb1, rb0, rb1);
    }
    __syncthreads();

    // --- Final combine + softmax: thread t < 32 owns batch row t ---
    if (tid < TCA_ROWS) {
        const float4 u = Red[tid];
        const float4 v = Red[32 + tid];
        const float q0 = u.x + v.x, q1 = u.y + v.y;
        const float q2 = u.z + v.z, q3 = u.w + v.w;
        const float S = q0 + q1 + q2 + q3;        // == ||x||^2 (U orthogonal)
        const float inv_s = 1.0f / S;
        const float p0 = q0 * inv_s, p1 = q1 * inv_s;
        const float p2 = q2 * inv_s, p3 = q3 * inv_s;
        const float mx = fmaxf(fmaxf(p0, p1), fmaxf(p2, p3));
        const float e0 = expf(p0 - mx), e1 = expf(p1 - mx);
        const float e2 = expf(p2 - mx), e3 = expf(p3 - mx);
        const float inv = 1.0f / (e0 + e1 + e2 + e3);
        reinterpret_cast<float4*>(out)[blockIdx.x * TCA_ROWS + tid] =
            make_float4(e0 * inv, e1 * inv, e2 * inv, e3 * inv);
    }
}

// ----------------------------- launch --------------------------------
extern "C" void kernel_launch(void* const* d_in, const int* in_sizes, int n_in,
                              void* d_out, int out_size) {
    const float* x   = (const float*)d_in[0];
    const float* QC1 = (const float*)d_in[1];
    const float* QC2 = (const float*)d_in[2];
    const float* QC3 = (const float*)d_in[3];
    const float* QP1 = (const float*)d_in[4];
    const float* QP2 = (const float*)d_in[5];
    const float* QP3 = (const float*)d_in[6];
    const float* QF  = (const float*)d_in[7];

    const int B = in_sizes[0] / 128;

    build_U_kernel<<<16, 256>>>(QC1, QC2, QC3, QP1, QP2, QP3, QF);

    cudaFuncSetAttribute(qcnn_mma_kernel,
                         cudaFuncAttributeMaxDynamicSharedMemorySize,
                         SM_TC_TOTAL);
    qcnn_mma_kernel<<<B / TCA_ROWS, TCA_THREADS, SM_TC_TOTAL>>>(
        x, (float*)d_out);
}

// round 15
// speedup vs baseline: 1.1533x; 1.0864x over previous
#include <cuda_runtime.h>
#include <cuda_bf16.h>
#include <cstdint>

// =====================================================================
// ATQCNN factorization:
//   U = fixed 128x128 orthogonal circuit matrix (wires 0..6; 7,8 inert)
//   Y[b] = U x[b];  q[b,k] = sum_{m&3==k} Y[b,m]^2;  out = softmax(q/sum q)
// Kernel 1: warp-per-basis register sim with FUSED two-qubit gate rounds
//   (RY_a, RY_b, CNOT(a,b) in one round: 3 parallel shfls + FMA tree),
//   U emitted as bf16 split via smem transpose + coalesced uint4 stores.
// Kernel 2 (R14/R11 apply, unchanged): mma.sync m16n8k16 bf16 GEMM,
//   3 accumulated passes, 128 CTAs x 4 warps, smem q-combine + softmax.
// =====================================================================

__device__ __align__(16) __nv_bfloat16 g_Uhi[128 * 128];  // [m][i] row-major
__device__ __align__(16) __nv_bfloat16 g_Ulo[128 * 128];  // [m][i] row-major

// --------------------- warp-MMA helpers -------------------------------
__device__ __forceinline__ uint32_t smem_to_u32(const void* p) {
    uint32_t a;
    asm("{ .reg .u64 t; cvta.to.shared.u64 t, %1; cvt.u32.u64 %0, t; }"
        : "=r"(a) : "l"(p));
    return a;
}
__device__ __forceinline__ void ldsm4(uint32_t& r0, uint32_t& r1,
                                      uint32_t& r2, uint32_t& r3, uint32_t a) {
    asm volatile("ldmatrix.sync.aligned.m8n8.x4.shared.b16 {%0,%1,%2,%3}, [%4];"
                 : "=r"(r0), "=r"(r1), "=r"(r2), "=r"(r3) : "r"(a));
}
__device__ __forceinline__ void ldsm2(uint32_t& r0, uint32_t& r1, uint32_t a) {
    asm volatile("ldmatrix.sync.aligned.m8n8.x2.shared.b16 {%0,%1}, [%2];"
                 : "=r"(r0), "=r"(r1) : "r"(a));
}
__device__ __forceinline__ void mma_bf16(float* d, const uint32_t* a,
                                         uint32_t b0, uint32_t b1) {
    asm volatile(
        "mma.sync.aligned.m16n8k16.row.col.f32.bf16.bf16.f32 "
        "{%0,%1,%2,%3}, {%4,%5,%6,%7}, {%8,%9}, {%0,%1,%2,%3};"
        : "+f"(d[0]), "+f"(d[1]), "+f"(d[2]), "+f"(d[3])
        : "r"(a[0]), "r"(a[1]), "r"(a[2]), "r"(a[3]), "r"(b0), "r"(b1));
}
__device__ __forceinline__ uint32_t pack_bf2(__nv_bfloat16 a, __nv_bfloat16 b) {
    __nv_bfloat162 t = __halves2bfloat162(a, b);
    return *reinterpret_cast<uint32_t*>(&t);
}

// --------------------- gate primitives (register sim) -----------------
// Amp index m (7 bits): bits[6:2] = lane, bits[1:0] = register r.
// Bit position of wire w is P = 6 - w.

template<int P>
__device__ __forceinline__ void ry_p(float a[4], float c, float s, int lane) {
    if constexpr (P == 0) {
        float n0 = c * a[0] - s * a[1];
        float n1 = fmaf(s, a[0], c * a[1]);
        float n2 = c * a[2] - s * a[3];
        float n3 = fmaf(s, a[2], c * a[3]);
        a[0] = n0; a[1] = n1; a[2] = n2; a[3] = n3;
    } else if constexpr (P == 1) {
        float n0 = c * a[0] - s * a[2];
        float n2 = fmaf(s, a[0], c * a[2]);
        float n1 = c * a[1] - s * a[3];
        float n3 = fmaf(s, a[1], c * a[3]);
        a[0] = n0; a[1] = n1; a[2] = n2; a[3] = n3;
    } else {
        constexpr int M = 1 << (P - 2);
        const float sgn = (lane & M) ? s : -s;
        #pragma unroll
        for (int r = 0; r < 4; ++r) {
            float pr = __shfl_xor_sync(0xffffffffu, a[r], M);
            a[r] = fmaf(sgn, pr, c * a[r]);
        }
    }
}
template<int W>
__device__ __forceinline__ void ry_w(float a[4], float2 cs, int lane) {
    ry_p<6 - W>(a, cs.x, cs.y, lane);
}

template<int PC, int PT>
__device__ __forceinline__ void cnot_p(float a[4], int lane) {
    if constexpr (PT >= 2) {
        constexpr int MT = 1 << (PT - 2);
        if constexpr (PC >= 2) {
            constexpr int MC = 1 << (PC - 2);
            const bool ctl = (lane & MC) != 0;
            #pragma unroll
            for (int r = 0; r < 4; ++r) {
                float pr = __shfl_xor_sync(0xffffffffu, a[r], MT);
                a[r] = ctl ? pr : a[r];
            }
        } else {
            #pragma unroll
            for (int r = 0; r < 4; ++r) {
                if ((r >> PC) & 1) {
                    a[r] = __shfl_xor_sync(0xffffffffu, a[r], MT);
                }
            }
        }
    } else {
        if constexpr (PC >= 2) {
            constexpr int MC = 1 << (PC - 2);
            const bool ctl = (lane & MC) != 0;
            if constexpr (PT == 0) {
                float t0 = a[0], t2 = a[2];
                a[0] = ctl ? a[1] : a[0];  a[1] = ctl ? t0 : a[1];
                a[2] = ctl ? a[3] : a[2];  a[3] = ctl ? t2 : a[3];
            } else {
                float t0 = a[0], t1 = a[1];
                a[0] = ctl ? a[2] : a[0];  a[2] = ctl ? t0 : a[2];
                a[1] = ctl ? a[3] : a[1];  a[3] = ctl ? t1 : a[3];
            }
        } else {
            if constexpr (PC == 1 && PT == 0) { float t = a[2]; a[2] = a[3]; a[3] = t; }
            else                              { float t = a[1]; a[1] = a[3]; a[3] = t; }
        }
    }
}
template<int C, int T>
__device__ __forceinline__ void cnot_w(float a[4], int lane) {
    cnot_p<6 - C, 6 - T>(a, lane);
}

// ---- FUSED two-qubit round: RY(A,ca,sa); RY(B,cb,sb); CNOT(A,B) ------
// out[a,b] = sum_{a',b'} Ra[a,a']·Rb[b^a,b']·v[a',b']
//   = ca·t0 + sa_s·t1,  sa_s = a? sa : -sa
//   t0 = cv·v   + cvB·vB,   t1 = cv·vA + cvB·vAB
//   sb_s = b? sb : -sb;  cv = a? -sb_s : cb;  cvB = a? cb : sb_s
template<int PA, int PB>
__device__ __forceinline__ void fg_p(float v[4], float ca, float sa,
                                     float cb, float sb, int lane) {
    float vA[4], vB[4], vAB[4];
    if constexpr (PA >= 2 && PB >= 2) {
        constexpr int MA = 1 << (PA - 2), MB = 1 << (PB - 2);
        #pragma unroll
        for (int r = 0; r < 4; ++r) {
            vA[r]  = __shfl_xor_sync(0xffffffffu, v[r], MA);
            vB[r]  = __shfl_xor_sync(0xffffffffu, v[r], MB);
            vAB[r] = __shfl_xor_sync(0xffffffffu, v[r], MA | MB);
        }
    } else if constexpr (PA >= 2) {            // B in-register
        constexpr int MA = 1 << (PA - 2);
        #pragma unroll
        for (int r = 0; r < 4; ++r)
            vA[r] = __shfl_xor_sync(0xffffffffu, v[r], MA);
        #pragma unroll
        for (int r = 0; r < 4; ++r) {
            vB[r]  = v[r ^ (1 << PB)];
            vAB[r] = vA[r ^ (1 << PB)];
        }
    } else if constexpr (PB >= 2) {            // A in-register
        constexpr int MB = 1 << (PB - 2);
        #pragma unroll
        for (int r = 0; r < 4; ++r)
            vB[r] = __shfl_xor_sync(0xffffffffu, v[r], MB);
        #pragma unroll
        for (int r = 0; r < 4; ++r) {
            vA[r]  = v[r ^ (1 << PA)];
            vAB[r] = vB[r ^ (1 << PA)];
        }
    } else {                                   // both in-register
        #pragma unroll
        for (int r = 0; r < 4; ++r) {
            vA[r]  = v[r ^ (1 << PA)];
            vB[r]  = v[r ^ (1 << PB)];
            vAB[r] = v[r ^ (1 << PA) ^ (1 << PB)];
        }
    }
    #pragma unroll
    for (int r = 0; r < 4; ++r) {
        const bool ab = (PA >= 2) ? (((lane >> (PA - 2)) & 1) != 0)
                                  : (((r >> PA) & 1) != 0);
        const bool bb = (PB >= 2) ? (((lane >> (PB - 2)) & 1) != 0)
                                  : (((r >> PB) & 1) != 0);
        const float sb_s = bb ? sb : -sb;
        const float cv   = ab ? -sb_s : cb;
        const float cvB  = ab ? cb : sb_s;
        const float sa_s = ab ? sa : -sa;
        const float t0 = fmaf(cv, v[r],  cvB * vB[r]);
        const float t1 = fmaf(cv, vA[r], cvB * vAB[r]);
        v[r] = fmaf(ca, t0, sa_s * t1);
    }
}
template<int WA, int WB>
__device__ __forceinline__ void fg_w(float v[4], float2 csa, float2 csb,
                                     int lane) {
    fg_p<6 - WA, 6 - WB>(v, csa.x, csa.y, csb.x, csb.y, lane);
}

template<int WA, int WB>
__device__ __forceinline__ void conv6f(float a[4], int lane,
                                       const float2* __restrict__ cs, int base) {
    #pragma unroll
    for (int q = 0; q < 6; ++q)
        fg_w<WA, WB>(a, cs[base + 2 * q], cs[base + 2 * q + 1], lane);
}

// ----------------------------- Kernel 1 ------------------------------
// 16 blocks x 256 threads; one warp per basis state (= input index i).
// Output transposed through smem -> one uint4 store per (m, array).
__global__ __launch_bounds__(256) void build_U_kernel(
        const float* __restrict__ QC1, const float* __restrict__ QC2,
        const float* __restrict__ QC3, const float* __restrict__ QP1,
        const float* __restrict__ QP2, const float* __restrict__ QP3,
        const float* __restrict__ QF) {
    __shared__ float2 cs[46];
    __shared__ __align__(16) __nv_bfloat16 sh[128][8];
    __shared__ __align__(16) __nv_bfloat16 sl[128][8];
    const int tid  = threadIdx.x;
    const int lane = tid & 31;
    const int wid  = tid >> 5;
    const int basis = blockIdx.x * 8 + wid;
    const float2 ID = make_float2(1.0f, 0.0f);   // identity "RY"

    if (tid < 46) {
        float ang;
        if      (tid < 12) ang = QC1[tid];
        else if (tid < 24) ang = QC2[tid - 12];
        else if (tid < 36) ang = QC3[tid - 24];
        else if (tid == 36) ang =  QP1[0];
        else if (tid == 37) ang =  QP1[1];
        else if (tid == 38) ang = -QP1[1];
        else if (tid == 39) ang =  QP2[0];
        else if (tid == 40) ang =  QP2[1];
        else if (tid == 41) ang = -QP2[1];
        else if (tid == 42) ang =  QP3[0];
        else if (tid == 43) ang =  QP3[1];
        else if (tid == 44) ang = -QP3[1];
        else               ang = QF[0] + QF[1] + QF[2] + QF[3];  // RY angles add
        float sn, c;
        sincosf(0.5f * ang, &sn, &c);
        cs[tid] = make_float2(c, sn);
    }
    __syncthreads();

    float a[4];
    #pragma unroll
    for (int r = 0; r < 4; ++r) a[r] = (lane * 4 + r == basis) ? 1.0f : 0.0f;

    // conv block 1: fused (RY_i, RY_{i+1%7}, CNOT) rounds
    conv6f<0,1>(a, lane, cs, 0);  conv6f<1,2>(a, lane, cs, 0);
    conv6f<2,3>(a, lane, cs, 0);  conv6f<3,4>(a, lane, cs, 0);
    conv6f<4,5>(a, lane, cs, 0);  conv6f<5,6>(a, lane, cs, 0);
    conv6f<6,0>(a, lane, cs, 0);
    // pool 1: fused (RY_i, RY_{i+3}, CNOT) + trailing RY
    fg_w<0,3>(a, cs[36], cs[37], lane);  ry_w<3>(a, cs[38], lane);
    fg_w<1,4>(a, cs[36], cs[37], lane);  ry_w<4>(a, cs[38], lane);
    fg_w<2,5>(a, cs[36], cs[37], lane);  ry_w<5>(a, cs[38], lane);
    // conv block 2
    conv6f<3,4>(a, lane, cs, 12);
    conv6f<4,5>(a, lane, cs, 12);
    conv6f<5,6>(a, lane, cs, 12);
    #pragma unroll
    for (int q = 0; q < 6; ++q) {            // i == 6: RY6, RY3, CNOT(6,0)
        fg_w<6,0>(a, cs[12 + 2 * q], ID, lane);   // RY6 + CNOT(6,0)
        ry_w<3>(a, cs[13 + 2 * q], lane);         // RY3 (commutes)
    }
    // pool 2
    fg_w<3,5>(a, cs[39], cs[40], lane);  ry_w<5>(a, cs[41], lane);
    fg_w<4,6>(a, cs[39], cs[40], lane);  ry_w<6>(a, cs[41], lane);
    // conv block 3 (reference bug preserved: CNOT(4,5))
    #pragma unroll
    for (int q = 0; q < 6; ++q) {
        fg_w<4,5>(a, ID, cs[24 + 2 * q], lane);   // RY5 + CNOT(4,5)
        ry_w<6>(a, cs[25 + 2 * q], lane);         // RY6 (commutes)
    }
    // pool 3 (reference bug preserved: CNOT(4,6))
    ry_w<5>(a, cs[42], lane);
    fg_w<4,6>(a, ID, cs[43], lane);               // RY6 + CNOT(4,6)
    ry_w<6>(a, cs[44], lane);
    // final: fused 4x RY(5) + CNOT(5,6); then CNOT(6,5)
    fg_w<5,6>(a, cs[45], ID, lane);
    cnot_w<6,5>(a, lane);

    // a[r] = U[m = lane*4 + r][i = basis]; split and transpose in smem.
    #pragma unroll
    for (int r = 0; r < 4; ++r) {
        const int m = lane * 4 + r;
        const __nv_bfloat16 h = __float2bfloat16(a[r]);
        sh[m][wid] = h;
        sl[m][wid] = __float2bfloat16(a[r] - __bfloat162float(h));
    }
    __syncthreads();

    // Coalesced stores: one uint4 (8 bf16 = this block's 8 columns).
    if (tid < 128) {
        *reinterpret_cast<uint4*>(&g_Uhi[tid * 128 + blockIdx.x * 8]) =
            *reinterpret_cast<const uint4*>(&sh[tid][0]);
    } else {
        const int m = tid - 128;
        *reinterpret_cast<uint4*>(&g_Ulo[m * 128 + blockIdx.x * 8]) =
            *reinterpret_cast<const uint4*>(&sl[m][0]);
    }
}

// ----------------------------- Kernel 2 ------------------------------
// 128 blocks x 128 threads (4 warps). Block = 32 batches. (R14 apply.)
#define TCA_THREADS 128
#define TCA_ROWS 32
#define PITCH 272
#define SM_XHI 0
#define SM_XLO (TCA_ROWS * PITCH)
#define SM_UHI (2 * TCA_ROWS * PITCH)
#define SM_ULO (2 * TCA_ROWS * PITCH + 128 * PITCH)
#define SM_RED (2 * TCA_ROWS * PITCH + 2 * 128 * PITCH)
#define SM_TC_TOTAL (SM_RED + 2 * TCA_ROWS * 16)

__global__ __launch_bounds__(TCA_THREADS) void qcnn_mma_kernel(
        const float* __restrict__ X, float* __restrict__ out) {
    extern __shared__ char smem[];
    const uint32_t smem_base = smem_to_u32(smem);
    float4* Red = reinterpret_cast<float4*>(smem + SM_RED);  // [nj][32]
    const int tid  = threadIdx.x;
    const int warp = tid >> 5;
    const int lane = tid & 31;

    // --- Stage X tile (32 rows) as bf16 hi/lo into padded smem ---
    const float4* gX4 =
        reinterpret_cast<const float4*>(X + (size_t)blockIdx.x * TCA_ROWS * 128);
    #pragma unroll
    for (int it = 0; it < 8; ++it) {
        const int idx = tid + it * TCA_THREADS;
        const float4 v = gX4[idx];
        const int row = idx >> 5;
        const int col = (idx & 31) << 2;
        const __nv_bfloat16 h0 = __float2bfloat16(v.x);
        const __nv_bfloat16 h1 = __float2bfloat16(v.y);
        const __nv_bfloat16 h2 = __float2bfloat16(v.z);
        const __nv_bfloat16 h3 = __float2bfloat16(v.w);
        const __nv_bfloat16 l0 = __float2bfloat16(v.x - __bfloat162float(h0));
        const __nv_bfloat16 l1 = __float2bfloat16(v.y - __bfloat162float(h1));
        const __nv_bfloat16 l2 = __float2bfloat16(v.z - __bfloat162float(h2));
        const __nv_bfloat16 l3 = __float2bfloat16(v.w - __bfloat162float(h3));
        const int off = row * PITCH + col * 2;
        *reinterpret_cast<uint2*>(smem + SM_XHI + off) =
            make_uint2(pack_bf2(h0, h1), pack_bf2(h2, h3));
        *reinterpret_cast<uint2*>(smem + SM_XLO + off) =
            make_uint2(pack_bf2(l0, l1), pack_bf2(l2, l3));
    }
    // --- Stage U hi/lo (128 rows) with uint4 loads ---
    const uint4* gUh = reinterpret_cast<const uint4*>(g_Uhi);
    const uint4* gUl = reinterpret_cast<const uint4*>(g_Ulo);
    #pragma unroll
    for (int it = 0; it < 16; ++it) {
        const int idx = tid + it * TCA_THREADS;
        const int row = idx >> 4;
        const int c16 = (idx & 15) * 16;
        const int off = row * PITCH + c16;
        *reinterpret_cast<uint4*>(smem + SM_UHI + off) = gUh[idx];
        *reinterpret_cast<uint4*>(smem + SM_ULO + off) = gUl[idx];
    }
    __syncthreads();

    // --- MMA mainloop ---
    const int mi = warp >> 1;
    const int nj = warp & 1;
    const int R0 = mi * 16;
    const int C0 = nj * 64;

    float d[8][4];
    #pragma unroll
    for (int j = 0; j < 8; ++j)
        { d[j][0] = 0.f; d[j][1] = 0.f; d[j][2] = 0.f; d[j][3] = 0.f; }

    const uint32_t aHi = smem_base + SM_XHI
        + (uint32_t)(R0 + (lane & 15)) * PITCH + (uint32_t)(lane >> 4) * 16;
    const uint32_t aLo = smem_base + SM_XLO
        + (uint32_t)(R0 + (lane & 15)) * PITCH + (uint32_t)(lane >> 4) * 16;
    const uint32_t bHi = smem_base + SM_UHI
        + (uint32_t)(C0 + (lane & 7)) * PITCH + (uint32_t)((lane >> 3) & 1) * 16;
    const uint32_t bLo = smem_base + SM_ULO
        + (uint32_t)(C0 + (lane & 7)) * PITCH + (uint32_t)((lane >> 3) & 1) * 16;

    // Fused passes 0+1: Xhi*Uhi + Xlo*Uhi (B fragments loaded once).
    #pragma unroll 1
    for (int ks = 0; ks < 8; ++ks) {
        uint32_t ah[4], al[4];
        ldsm4(ah[0], ah[1], ah[2], ah[3], aHi + ks * 32);
        ldsm4(al[0], al[1], al[2], al[3], aLo + ks * 32);
        const uint32_t bks = bHi + ks * 32;
        #pragma unroll
        for (int j = 0; j < 8; ++j) {
            uint32_t b0, b1;
            ldsm2(b0, b1, bks + j * (8 * PITCH));
            mma_bf16(d[j], ah, b0, b1);
            mma_bf16(d[j], al, b0, b1);
        }
    }
    // Pass 2: Xhi*Ulo.
    #pragma unroll 1
    for (int ks = 0; ks < 8; ++ks) {
        uint32_t ah[4];
        ldsm4(ah[0], ah[1], ah[2], ah[3], aHi + ks * 32);
        const uint32_t bks = bLo + ks * 32;
        #pragma unroll
        for (int j = 0; j < 8; ++j) {
            uint32_t b0, b1;
            ldsm2(b0, b1, bks + j * (8 * PITCH));
            mma_bf16(d[j], ah, b0, b1);
        }
    }

    // --- In-warp q reduction ---
    float qa0 = 0.f, qa1 = 0.f;
    float qb0 = 0.f, qb1 = 0.f;
    #pragma unroll
    for (int j = 0; j < 8; ++j) {
        qa0 = fmaf(d[j][0], d[j][0], qa0);
        qa1 = fmaf(d[j][1], d[j][1], qa1);
        qb0 = fmaf(d[j][2], d[j][2], qb0);
        qb1 = fmaf(d[j][3], d[j][3], qb1);
    }
    qa0 += __shfl_xor_sync(0xffffffffu, qa0, 2);
    qa1 += __shfl_xor_sync(0xffffffffu, qa1, 2);
    qb0 += __shfl_xor_sync(0xffffffffu, qb0, 2);
    qb1 += __shfl_xor_sync(0xffffffffu, qb1, 2);
    const float ra0 = __shfl_xor_sync(0xffffffffu, qa0, 1);
    const float ra1 = __shfl_xor_sync(0xffffffffu, qa1, 1);
    const float rb0 = __shfl_xor_sync(0xffffffffu, qb0, 1);
    const float rb1 = __shfl_xor_sync(0xffffffffu, qb1, 1);

    if ((lane & 3) == 0) {
        const int r = lane >> 2;
        Red[nj * 32 + R0 + r]     = make_float4(qa0, qa1, ra0, ra1);
        Red[nj * 32 + R0 + r + 8] = make_float4(qb0, qb1, rb0, rb1);
    }
    __syncthreads();

    // --- Final combine + softmax: thread t < 32 owns batch row t ---
    if (tid < TCA_ROWS) {
        const float4 u = Red[tid];
        const float4 v = Red[32 + tid];
        const float q0 = u.x + v.x, q1 = u.y + v.y;
        const float q2 = u.z + v.z, q3 = u.w + v.w;
        const float S = q0 + q1 + q2 + q3;        // == ||x||^2 (U orthogonal)
        const float inv_s = 1.0f / S;
        const float p0 = q0 * inv_s, p1 = q1 * inv_s;
        const float p2 = q2 * inv_s, p3 = q3 * inv_s;
        const float mx = fmaxf(fmaxf(p0, p1), fmaxf(p2, p3));
        const float e0 = expf(p0 - mx), e1 = expf(p1 - mx);
        const float e2 = expf(p2 - mx), e3 = expf(p3 - mx);
        const float inv = 1.0f / (e0 + e1 + e2 + e3);
        reinterpret_cast<float4*>(out)[blockIdx.x * TCA_ROWS + tid] =
            make_float4(e0 * inv, e1 * inv, e2 * inv, e3 * inv);
    }
}

// ----------------------------- launch --------------------------------
extern "C" void kernel_launch(void* const* d_in, const int* in_sizes, int n_in,
                              void* d_out, int out_size) {
    const float* x   = (const float*)d_in[0];
    const float* QC1 = (const float*)d_in[1];
    const float* QC2 = (const float*)d_in[2];
    const float* QC3 = (const float*)d_in[3];
    const float* QP1 = (const float*)d_in[4];
    const float* QP2 = (const float*)d_in[5];
    const float* QP3 = (const float*)d_in[6];
    const float* QF  = (const float*)d_in[7];

    const int B = in_sizes[0] / 128;

    build_U_kernel<<<16, 256>>>(QC1, QC2, QC3, QP1, QP2, QP3, QF);

    cudaFuncSetAttribute(qcnn_mma_kernel,
                         cudaFuncAttributeMaxDynamicSharedMemorySize,
                         SM_TC_TOTAL);
    qcnn_mma_kernel<<<B / TCA_ROWS, TCA_THREADS, SM_TC_TOTAL>>>(
        x, (float*)d_out);
}